// round 1
// baseline (speedup 1.0000x reference)
#include <cuda_runtime.h>

#define S_GRID 28
#define SS 784            // 28*28
#define NC 80
#define BB 2
#define MAXB 50
#define PRED_C 90         // BB*5 + NC

__device__ float g_partial[4096];

__global__ __launch_bounds__(256) void yolo_loss_kernel(
    const float* __restrict__ pred,
    const float* __restrict__ tgt)
{
    const int b   = blockIdx.x;
    const int tid = threadIdx.x;

    __shared__ float4   s_gtbox[SS];
    __shared__ float    s_bestiou[SS];
    __shared__ int      s_resp[SS];          // -1 = no object
    __shared__ unsigned s_cls[SS][3];        // 80-bit class mask
    __shared__ int      s_objlist[MAXB + 2];
    __shared__ int      s_nobj;
    // per-target precomputed records
    __shared__ int      r_valid[MAXB];
    __shared__ int      r_cell[MAXB];
    __shared__ float4   r_box[MAXB];         // cx_rel, cy_rel, w, h
    __shared__ float    r_best[MAXB];
    __shared__ int      r_bestj[MAXB];
    __shared__ float    s_red[256];

    const float cell = 1.0f / 28.0f;

    for (int c = tid; c < SS; c += 256) {
        s_resp[c]    = -1;
        s_bestiou[c] = 0.0f;
        s_cls[c][0] = 0u; s_cls[c][1] = 0u; s_cls[c][2] = 0u;
    }
    __syncthreads();

    const float* pb = pred + (size_t)b * SS * PRED_C;

    // ---- Phase 1a: parallel per-target precompute (state-independent) ----
    if (tid < MAXB) {
        const float* tt = tgt + ((size_t)b * MAXB + tid) * 5;
        float cls = tt[0];
        int valid = (cls >= 0.0f) ? 1 : 0;
        r_valid[tid] = valid;
        if (valid) {
            float cx = tt[1], cy = tt[2], w = tt[3], h = tt[4];
            int ci  = min(max((int)cls, 0), NC - 1);
            int col = min((int)(cx / cell), S_GRID - 1);
            int row = min((int)(cy / cell), S_GRID - 1);
            float cxr = cx / cell - (float)col;
            float cyr = cy / cell - (float)row;
            int cc = row * S_GRID + col;
            r_cell[tid] = cc;
            r_box[tid]  = make_float4(cxr, cyr, w, h);

            const float* pp = pb + cc * PRED_C;
            float gx1 = cx - w * 0.5f, gy1 = cy - h * 0.5f;
            float gx2 = cx + w * 0.5f, gy2 = cy + h * 0.5f;
            float garea = fmaxf(gx2 - gx1, 0.0f) * fmaxf(gy2 - gy1, 0.0f);
            float iou[2];
            #pragma unroll
            for (int j = 0; j < 2; j++) {
                float px = (pp[5*j + 0] + (float)col) * cell;
                float py = (pp[5*j + 1] + (float)row) * cell;
                float pw = pp[5*j + 2], ph = pp[5*j + 3];
                float px1 = px - pw * 0.5f, py1 = py - ph * 0.5f;
                float px2 = px + pw * 0.5f, py2 = py + ph * 0.5f;
                float iw = fmaxf(fminf(px2, gx2) - fmaxf(px1, gx1), 0.0f);
                float ih = fmaxf(fminf(py2, gy2) - fmaxf(py1, gy1), 0.0f);
                float inter = iw * ih;
                float uni = fmaxf(px2 - px1, 0.0f) * fmaxf(py2 - py1, 0.0f)
                          + garea - inter;
                iou[j] = inter / (uni + 1e-6f);
            }
            // jnp.argmax -> first max index on tie
            r_bestj[tid] = (iou[1] > iou[0]) ? 1 : 0;
            r_best[tid]  = fmaxf(iou[0], iou[1]);
            // class one-hot is a commutative max -> order free
            atomicOr(&s_cls[cc][ci >> 5], 1u << (ci & 31));
        }
    }
    __syncthreads();

    // ---- Phase 1b: sequential compare-and-set replay (SMEM only) ----
    if (tid == 0) {
        for (int t = 0; t < MAXB; t++) {
            if (!r_valid[t]) continue;
            int c = r_cell[t];
            if (s_resp[c] < 0 || r_best[t] > s_bestiou[c]) {
                s_gtbox[c]   = r_box[t];
                s_bestiou[c] = r_best[t];
                s_resp[c]    = r_bestj[t];
            }
        }
    }
    __syncthreads();

    // ---- Deterministic compaction of object cells (warp 0 ballot scan) ----
    if (tid < 32) {
        int count = 0;
        for (int cb = 0; cb < SS; cb += 32) {
            int c = cb + tid;
            bool p = (c < SS) && (s_resp[c] >= 0);
            unsigned m = __ballot_sync(0xffffffffu, p);
            if (p) s_objlist[count + __popc(m & ((1u << tid) - 1u))] = c;
            count += __popc(m);
        }
        if (tid == 0) s_nobj = count;
    }
    __syncthreads();
    const int nobj = s_nobj;

    float acc_noobj = 0.0f, acc_obj = 0.0f, acc_coord = 0.0f, acc_cls = 0.0f;

    // ---- Phase 2a: noobj confidence over ALL cells, both boxes ----
    for (int c = tid; c < SS; c += 256) {
        float c0 = pb[c * PRED_C + 4];
        float c1 = pb[c * PRED_C + 9];
        acc_noobj += c0 * c0 + c1 * c1;
    }

    // ---- Phase 2b: object cells: coord (CIoU) + obj + noobj correction ----
    for (int i = tid; i < nobj; i += 256) {
        int c = s_objlist[i];
        const float* pp = pb + c * PRED_C;
        int r = s_resp[c];
        float bx = pp[5*r + 0], by = pp[5*r + 1];
        float bw = pp[5*r + 2], bh = pp[5*r + 3], bc = pp[5*r + 4];
        acc_noobj -= bc * bc;                 // responsible box excluded
        float d = bc - s_bestiou[c];
        acc_obj += d * d;

        int row = c / S_GRID, col = c % S_GRID;
        float4 g = s_gtbox[c];
        float px = (bx + (float)col) * cell, py = (by + (float)row) * cell;
        float pw = fabsf(bw), ph = fabsf(bh);
        float gx = (g.x + (float)col) * cell, gy = (g.y + (float)row) * cell;
        float gw = g.z, gh = g.w;

        float px1 = px - pw * 0.5f, py1 = py - ph * 0.5f;
        float px2 = px + pw * 0.5f, py2 = py + ph * 0.5f;
        float gx1 = gx - gw * 0.5f, gy1 = gy - gh * 0.5f;
        float gx2 = gx + gw * 0.5f, gy2 = gy + gh * 0.5f;
        float iw = fmaxf(fminf(px2, gx2) - fmaxf(px1, gx1), 0.0f);
        float ih = fmaxf(fminf(py2, gy2) - fmaxf(py1, gy1), 0.0f);
        float inter = iw * ih;
        float ap = fmaxf(px2 - px1, 0.0f) * fmaxf(py2 - py1, 0.0f);
        float ag = fmaxf(gx2 - gx1, 0.0f) * fmaxf(gy2 - gy1, 0.0f);
        float uni = ap + ag - inter;
        float iou = inter / (uni + 1e-7f);
        float rho2 = (px - gx) * (px - gx) + (py - gy) * (py - gy);
        float cw = fmaxf(px2, gx2) - fminf(px1, gx1);
        float ch = fmaxf(py2, gy2) - fminf(py1, gy1);
        float c2 = cw * cw + ch * ch + 1e-7f;
        float dv = atanf(gw / (gh + 1e-7f)) - atanf(pw / (ph + 1e-7f));
        float v = 0.40528473456935108577f * dv * dv;   // 4/pi^2
        float alpha = v / (1.0f - iou + v + 1e-7f);
        acc_coord += 1.0f - iou + rho2 / c2 + alpha * v;
    }

    // ---- Phase 2c: class BCE over (obj cell, class) pairs ----
    for (int idx = tid; idx < nobj * NC; idx += 256) {
        int i  = idx / NC;
        int cc = idx - i * NC;
        int c  = s_objlist[i];
        float x = pb[c * PRED_C + BB * 5 + cc];
        float gflag = ((s_cls[c][cc >> 5] >> (cc & 31)) & 1u) ? 1.0f : 0.0f;
        acc_cls += fmaxf(x, 0.0f) - x * gflag + log1pf(expf(-fabsf(x)));
    }

    // ---- Block reduction (deterministic tree) ----
    float total = 5.0f * acc_coord + acc_obj + 0.1f * acc_noobj + acc_cls;
    s_red[tid] = total;
    __syncthreads();
    #pragma unroll
    for (int s = 128; s > 0; s >>= 1) {
        if (tid < s) s_red[tid] += s_red[tid + s];
        __syncthreads();
    }
    if (tid == 0) g_partial[b] = s_red[0];
}

__global__ void yolo_reduce_kernel(float* __restrict__ out, int batch) {
    __shared__ float s[512];
    int tid = threadIdx.x;
    float v = 0.0f;
    for (int i = tid; i < batch; i += 512) v += g_partial[i];
    s[tid] = v;
    __syncthreads();
    #pragma unroll
    for (int k = 256; k > 0; k >>= 1) {
        if (tid < k) s[tid] += s[tid + k];
        __syncthreads();
    }
    if (tid == 0) out[0] = s[0] / (float)batch;
}

extern "C" void kernel_launch(void* const* d_in, const int* in_sizes, int n_in,
                              void* d_out, int out_size)
{
    const float* pred = (const float*)d_in[0];
    const float* tgt  = (const float*)d_in[1];
    int batch = in_sizes[0] / (SS * PRED_C);
    if (batch > 4096) batch = 4096;
    yolo_loss_kernel<<<batch, 256>>>(pred, tgt);
    yolo_reduce_kernel<<<1, 512>>>((float*)d_out, batch);
}

// round 2
// speedup vs baseline: 1.2424x; 1.2424x over previous
#include <cuda_runtime.h>

#define S_GRID 28
#define SS 784            // 28*28
#define NC 80
#define BB 2
#define MAXB 50
#define PRED_C 90         // BB*5 + NC

__device__ float g_partial[4096];
__device__ int   g_count = 0;

__global__ __launch_bounds__(256) void yolo_loss_kernel(
    const float* __restrict__ pred,
    const float* __restrict__ tgt,
    float* __restrict__ out,
    int batch)
{
    const int b   = blockIdx.x;
    const int tid = threadIdx.x;

    __shared__ unsigned long long s_key[SS];   // (bits(best)<<32)|(63-t); 0 = empty
    __shared__ float4   s_gtbox[SS];
    __shared__ float    s_bestiou[SS];
    __shared__ int      s_resp[SS];            // winner's best box idx
    __shared__ unsigned s_cls[SS][3];          // 80-bit class mask
    __shared__ int      s_objlist[MAXB + 2];
    __shared__ int      s_nobj;
    __shared__ float    s_red[8];

    const float cell = 1.0f / 28.0f;
    const float* pb = pred + (size_t)b * SS * PRED_C;

    // ---- issue the target loads ASAP (2-deep dependent DRAM chain) ----
    float t0 = 0.f, t1 = 0.f, t2 = 0.f, t3 = 0.f, t4 = -1.f;
    if (tid < MAXB) {
        const float* tt = tgt + ((size_t)b * MAXB + tid) * 5;
        t4 = tt[0]; t0 = tt[1]; t1 = tt[2]; t2 = tt[3]; t3 = tt[4];
    }

    // ---- noobj confidence sweep: independent of all target state ----
    float acc_noobj = 0.0f;
    #pragma unroll
    for (int k = 0; k < 4; k++) {
        int c = tid + k * 256;
        if (c < SS) {
            float c0 = __ldg(pb + c * PRED_C + 4);
            float c1 = __ldg(pb + c * PRED_C + 9);
            acc_noobj += c0 * c0 + c1 * c1;
        }
    }

    // ---- SMEM init ----
    for (int c = tid; c < SS; c += 256) {
        s_key[c]  = 0ull;
        s_resp[c] = -1;
        s_cls[c][0] = 0u; s_cls[c][1] = 0u; s_cls[c][2] = 0u;
    }
    __syncthreads();

    // ---- per-target precompute + atomicMax race (replaces serial scan) ----
    int   my_cell = -1, my_bestj = 0;
    float my_best = 0.f;
    float4 my_box;
    unsigned long long my_key = 0ull;
    if (tid < MAXB && t4 >= 0.0f) {
        float cx = t0, cy = t1, w = t2, h = t3;
        int ci  = min(max((int)t4, 0), NC - 1);
        int col = min((int)(cx / cell), S_GRID - 1);
        int row = min((int)(cy / cell), S_GRID - 1);
        float cxr = cx / cell - (float)col;
        float cyr = cy / cell - (float)row;
        my_cell = row * S_GRID + col;
        my_box  = make_float4(cxr, cyr, w, h);

        const float* pp = pb + my_cell * PRED_C;
        float gx1 = cx - w * 0.5f, gy1 = cy - h * 0.5f;
        float gx2 = cx + w * 0.5f, gy2 = cy + h * 0.5f;
        float garea = fmaxf(gx2 - gx1, 0.0f) * fmaxf(gy2 - gy1, 0.0f);
        float iou[2];
        #pragma unroll
        for (int j = 0; j < 2; j++) {
            float px = (pp[5*j + 0] + (float)col) * cell;
            float py = (pp[5*j + 1] + (float)row) * cell;
            float pw = pp[5*j + 2], ph = pp[5*j + 3];
            float px1 = px - pw * 0.5f, py1 = py - ph * 0.5f;
            float px2 = px + pw * 0.5f, py2 = py + ph * 0.5f;
            float iw = fmaxf(fminf(px2, gx2) - fmaxf(px1, gx1), 0.0f);
            float ih = fmaxf(fminf(py2, gy2) - fmaxf(py1, gy1), 0.0f);
            float inter = iw * ih;
            float uni = fmaxf(px2 - px1, 0.0f) * fmaxf(py2 - py1, 0.0f)
                      + garea - inter;
            iou[j] = inter / (uni + 1e-6f);
        }
        my_bestj = (iou[1] > iou[0]) ? 1 : 0;      // first-index tie break
        my_best  = fmaxf(iou[0], iou[1]);
        // scan semantics == first index achieving the max best per cell:
        // strictly-greater steals; equal does not. Key orders by (best, -t).
        my_key = ((unsigned long long)__float_as_uint(my_best) << 32)
               | (unsigned long long)(63 - tid);
        atomicMax(&s_key[my_cell], my_key);
        atomicOr(&s_cls[my_cell][ci >> 5], 1u << (ci & 31));
    }
    __syncthreads();

    // winners write their cell state (unique per cell)
    if (my_key != 0ull && s_key[my_cell] == my_key) {
        s_gtbox[my_cell]   = my_box;
        s_bestiou[my_cell] = my_best;
        s_resp[my_cell]    = my_bestj;
    }
    __syncthreads();

    // ---- deterministic compaction of object cells (warp 0 ballot scan) ----
    if (tid < 32) {
        int count = 0;
        #pragma unroll
        for (int cb = 0; cb < SS; cb += 32) {
            int c = cb + tid;
            bool p = (c < SS) && (s_resp[c] >= 0);
            unsigned m = __ballot_sync(0xffffffffu, p);
            if (p) s_objlist[count + __popc(m & ((1u << tid) - 1u))] = c;
            count += __popc(m);
        }
        if (tid == 0) s_nobj = count;
    }
    __syncthreads();
    const int nobj = s_nobj;

    float acc_obj = 0.0f, acc_coord = 0.0f, acc_cls = 0.0f;

    // ---- object cells: CIoU + obj conf + noobj correction ----
    for (int i = tid; i < nobj; i += 256) {
        int c = s_objlist[i];
        const float* pp = pb + c * PRED_C;
        int r = s_resp[c];
        float bx = pp[5*r + 0], by = pp[5*r + 1];
        float bw = pp[5*r + 2], bh = pp[5*r + 3], bc = pp[5*r + 4];
        acc_noobj -= bc * bc;                 // responsible box excluded
        float d = bc - s_bestiou[c];
        acc_obj += d * d;

        int row = c / S_GRID, col = c % S_GRID;
        float4 g = s_gtbox[c];
        float px = (bx + (float)col) * cell, py = (by + (float)row) * cell;
        float pw = fabsf(bw), ph = fabsf(bh);
        float gx = (g.x + (float)col) * cell, gy = (g.y + (float)row) * cell;
        float gw = g.z, gh = g.w;

        float px1 = px - pw * 0.5f, py1 = py - ph * 0.5f;
        float px2 = px + pw * 0.5f, py2 = py + ph * 0.5f;
        float gx1 = gx - gw * 0.5f, gy1 = gy - gh * 0.5f;
        float gx2 = gx + gw * 0.5f, gy2 = gy + gh * 0.5f;
        float iw = fmaxf(fminf(px2, gx2) - fmaxf(px1, gx1), 0.0f);
        float ih = fmaxf(fminf(py2, gy2) - fmaxf(py1, gy1), 0.0f);
        float inter = iw * ih;
        float ap = fmaxf(px2 - px1, 0.0f) * fmaxf(py2 - py1, 0.0f);
        float ag = fmaxf(gx2 - gx1, 0.0f) * fmaxf(gy2 - gy1, 0.0f);
        float uni = ap + ag - inter;
        float iou = inter / (uni + 1e-7f);
        float rho2 = (px - gx) * (px - gx) + (py - gy) * (py - gy);
        float cw = fmaxf(px2, gx2) - fminf(px1, gx1);
        float ch = fmaxf(py2, gy2) - fminf(py1, gy1);
        float c2 = cw * cw + ch * ch + 1e-7f;
        float dv = atanf(gw / (gh + 1e-7f)) - atanf(pw / (ph + 1e-7f));
        float v = 0.40528473456935108577f * dv * dv;   // 4/pi^2
        float alpha = v / (1.0f - iou + v + 1e-7f);
        acc_coord += 1.0f - iou + rho2 / c2 + alpha * v;
    }

    // ---- class BCE over (obj cell, class) pairs ----
    for (int idx = tid; idx < nobj * NC; idx += 256) {
        int i  = idx / NC;
        int cc = idx - i * NC;
        int c  = s_objlist[i];
        float x = __ldg(pb + c * PRED_C + BB * 5 + cc);
        float gflag = ((s_cls[c][cc >> 5] >> (cc & 31)) & 1u) ? 1.0f : 0.0f;
        acc_cls += fmaxf(x, 0.0f) - x * gflag + log1pf(expf(-fabsf(x)));
    }

    // ---- block reduction: shuffle within warp, tree across warps ----
    float total = 5.0f * acc_coord + acc_obj + 0.1f * acc_noobj + acc_cls;
    #pragma unroll
    for (int off = 16; off > 0; off >>= 1)
        total += __shfl_down_sync(0xffffffffu, total, off);
    if ((tid & 31) == 0) s_red[tid >> 5] = total;
    __syncthreads();
    if (tid == 0) {
        float v = ((s_red[0] + s_red[1]) + (s_red[2] + s_red[3]))
                + ((s_red[4] + s_red[5]) + (s_red[6] + s_red[7]));
        g_partial[b] = v;
        __threadfence();
    }
    __syncthreads();

    // ---- last block performs the final deterministic reduction ----
    __shared__ int s_last;
    if (tid == 0) s_last = (atomicAdd(&g_count, 1) == batch - 1) ? 1 : 0;
    __syncthreads();
    if (s_last) {
        // fixed-order tree over g_partial: value is replay-deterministic
        __shared__ float s_fin[256];
        float v = 0.0f;
        for (int i = tid; i < batch; i += 256) v += g_partial[i];
        s_fin[tid] = v;
        __syncthreads();
        #pragma unroll
        for (int k = 128; k > 0; k >>= 1) {
            if (tid < k) s_fin[tid] += s_fin[tid + k];
            __syncthreads();
        }
        if (tid == 0) {
            out[0] = s_fin[0] / (float)batch;
            g_count = 0;                        // reset for next graph replay
        }
    }
}

extern "C" void kernel_launch(void* const* d_in, const int* in_sizes, int n_in,
                              void* d_out, int out_size)
{
    const float* pred = (const float*)d_in[0];
    const float* tgt  = (const float*)d_in[1];
    int batch = in_sizes[0] / (SS * PRED_C);
    if (batch > 4096) batch = 4096;
    yolo_loss_kernel<<<batch, 256>>>(pred, tgt, (float*)d_out, batch);
}